// round 15
// baseline (speedup 1.0000x reference)
#include <cuda_runtime.h>
#include <cuda_fp16.h>
#include <stdint.h>
#include <math.h>

#define S_LEN   2048
#define D_MODEL 1024
#define NHEAD   16
#define HDIM    64

typedef __half fp16;

// ---------------------------------------------------------------------------
// Device-global scratch (allocation-free, zero-init at load).
// ---------------------------------------------------------------------------
static __device__ fp16  g_iq[S_LEN * D_MODEL], g_ik[S_LEN * D_MODEL], g_iv[S_LEN * D_MODEL];
static __device__ fp16  g_wq[D_MODEL * D_MODEL], g_wk[D_MODEL * D_MODEL];
static __device__ fp16  g_wv[D_MODEL * D_MODEL], g_wo[D_MODEL * D_MODEL];
static __device__ fp16  g_qh[S_LEN * D_MODEL];                          // q hi, pre-scaled 0.125
static __device__ fp16  g_kh[S_LEN * D_MODEL];                          // k hi
static __device__ fp16  g_vt[D_MODEL * S_LEN];                          // V^T hi [h*64+v][t]
static __device__ fp16  g_zh[S_LEN * D_MODEL];                          // Z hi
static __device__ float g_part[NHEAD * 16 * S_LEN];
static __device__ float g_cpart[NHEAD * 16 * HDIM];                     // [h][seg][v]

// ---------------------------------------------------------------------------
// PTX helpers (generic sm_80-class PTX, legal under compute_103)
// ---------------------------------------------------------------------------
__device__ __forceinline__ uint32_t smem_u32(const void* p) {
    uint32_t a;
    asm("{ .reg .u64 t; cvta.to.shared.u64 t, %1; cvt.u32.u64 %0, t; }" : "=r"(a) : "l"(p));
    return a;
}
__device__ __forceinline__ void cp_async16(uint32_t dst, const void* src) {
    asm volatile("cp.async.cg.shared.global [%0], [%1], 16;" :: "r"(dst), "l"(src));
}
__device__ __forceinline__ void cp_commit() {
    asm volatile("cp.async.commit_group;" ::: "memory");
}
template<int N> __device__ __forceinline__ void cp_wait() {
    asm volatile("cp.async.wait_group %0;" :: "n"(N) : "memory");
}
__device__ __forceinline__ void bar_sync(int id, int cnt) {
    asm volatile("bar.sync %0, %1;" :: "r"(id), "r"(cnt) : "memory");
}

#define LDSM_X4(r, addr) \
    asm volatile("ldmatrix.sync.aligned.m8n8.x4.shared.b16 {%0,%1,%2,%3}, [%4];" \
        : "=r"((r)[0]), "=r"((r)[1]), "=r"((r)[2]), "=r"((r)[3]) : "r"(addr))

__device__ __forceinline__ void mma16816(float* c, const uint32_t* a, const uint32_t* b) {
    asm volatile(
        "mma.sync.aligned.m16n8k16.row.col.f32.f16.f16.f32 "
        "{%0,%1,%2,%3}, {%4,%5,%6,%7}, {%8,%9}, {%0,%1,%2,%3};"
        : "+f"(c[0]), "+f"(c[1]), "+f"(c[2]), "+f"(c[3])
        : "r"(a[0]), "r"(a[1]), "r"(a[2]), "r"(a[3]), "r"(b[0]), "r"(b[1]));
}

__device__ __forceinline__ uint32_t pack2h(float v0, float v1) {
    uint32_t r;
    asm("cvt.rn.f16x2.f32 %0, %1, %2;" : "=r"(r) : "f"(v1), "f"(v0));
    return r;
}

// ---------------------------------------------------------------------------
// 1-pass GEMM mainloop: 128x128 tile, BK=32, 3-stage cp.async pipeline.
// ---------------------------------------------------------------------------
#define PITCHB 80
#define AB128 (128 * PITCHB)
#define STAGE1 (2 * AB128)             // 20480
#define SMEM_PROJ (3 * STAGE1)         // 61440

__device__ __forceinline__ void mma_mainloop128_1p(
    uint32_t sb, float (&acc)[2][8][4],
    const fp16* __restrict__ Ahi, int lda, int arow0,
    const fp16* __restrict__ Bhi, int ldb, int brow0,
    int nchunks)
{
    const int tid = threadIdx.x, lane = tid & 31, wid = tid >> 5;
    const int wm = (wid & 3) * 32, wn = (wid >> 2) * 64;

    auto load = [&](int c) {
        uint32_t s = sb + (uint32_t)(c % 3) * STAGE1;
        const int k0 = c * 32;
        for (int i = tid; i < 128 * 4; i += 256) {
            int r = i >> 2, cb = (i & 3) << 4;
            cp_async16(s + (uint32_t)(r * PITCHB + cb),
                       (const char*)(Ahi + (size_t)(arow0 + r) * lda + k0) + cb);
            cp_async16(s + AB128 + (uint32_t)(r * PITCHB + cb),
                       (const char*)(Bhi + (size_t)(brow0 + r) * ldb + k0) + cb);
        }
        cp_commit();
    };

    const uint32_t aoff = (uint32_t)((wm + (lane & 15)) * PITCHB + ((lane & 16) ? 16 : 0));
    const uint32_t boff = (uint32_t)((wn + (lane & 7) + ((lane & 16) ? 8 : 0)) * PITCHB +
                                     ((lane & 8) ? 16 : 0));

    load(0);
    if (nchunks > 1) load(1);
    for (int c = 0; c < nchunks; c++) {
        if (c + 2 < nchunks) { load(c + 2); cp_wait<2>(); }
        else if (c + 1 < nchunks) cp_wait<1>();
        else cp_wait<0>();
        __syncthreads();
        uint32_t s  = sb + (uint32_t)(c % 3) * STAGE1;
        uint32_t sa = s + aoff;
        uint32_t sbb = s + AB128 + boff;
#pragma unroll
        for (int ks = 0; ks < 2; ks++) {
            const uint32_t ko = (uint32_t)(ks * 32);
            uint32_t ah[2][4];
            LDSM_X4(ah[0], sa + ko);
            LDSM_X4(ah[1], sa + 16 * PITCHB + ko);
            uint32_t bh[8][2];
#pragma unroll
            for (int p = 0; p < 4; p++) {
                uint32_t r4[4];
                LDSM_X4(r4, sbb + (uint32_t)(p * 16 * PITCHB) + ko);
                bh[2*p][0] = r4[0]; bh[2*p][1] = r4[1];
                bh[2*p+1][0] = r4[2]; bh[2*p+1][1] = r4[3];
            }
#pragma unroll
            for (int f = 0; f < 2; f++)
#pragma unroll
                for (int j = 0; j < 8; j++)
                    mma16816(acc[f][j], ah[f], bh[j]);
        }
        __syncthreads();
    }
}

// ---------------------------------------------------------------------------
// Merged Q/K/V projections: grid(8, 16, 3). z: 0=Q (scale 0.125), 1=K, 2=V(T).
// ---------------------------------------------------------------------------
__global__ __launch_bounds__(256, 2) void gemm_qkv(
    const float* __restrict__ bq, const float* __restrict__ bk, const float* __restrict__ bv)
{
    extern __shared__ char smem[];
    uint32_t sb = smem_u32(smem);
    const int z = blockIdx.z;
    const int row0 = blockIdx.y << 7, col0 = blockIdx.x << 7;

    const fp16* Ah = (z == 0) ? g_iq : (z == 1) ? g_ik : g_iv;
    const fp16* Bh = (z == 0) ? g_wq : (z == 1) ? g_wk : g_wv;
    const float* bias = (z == 0) ? bq : (z == 1) ? bk : bv;
    const float scale = (z == 0) ? 0.125f : 1.0f;

    float acc[2][8][4];
#pragma unroll
    for (int f = 0; f < 2; f++)
#pragma unroll
        for (int j = 0; j < 8; j++)
#pragma unroll
            for (int q = 0; q < 4; q++) acc[f][j][q] = 0.f;

    mma_mainloop128_1p(sb, acc, Ah, D_MODEL, row0, Bh, D_MODEL, col0, D_MODEL / 32);

    const int lane = threadIdx.x & 31, wid = threadIdx.x >> 5;
    const int wm = (wid & 3) * 32, wn = (wid >> 2) * 64;
    const int rb = row0 + wm + (lane >> 2);
    const int cb = col0 + wn + (lane & 3) * 2;
    fp16* ohi = (z == 0) ? g_qh : g_kh;
#pragma unroll
    for (int f = 0; f < 2; f++)
#pragma unroll
        for (int j = 0; j < 8; j++)
#pragma unroll
            for (int rh = 0; rh < 2; rh++) {
                const int r = rb + f * 16 + rh * 8;
                const int col = cb + j * 8;
                float v0 = (acc[f][j][rh * 2 + 0] + bias[col])     * scale;
                float v1 = (acc[f][j][rh * 2 + 1] + bias[col + 1]) * scale;
                uint32_t hp = pack2h(v0, v1);
                if (z < 2) {
                    *(uint32_t*)(ohi + (size_t)r * D_MODEL + col) = hp;
                } else {
                    g_vt[(size_t)col * S_LEN + r]       = __ushort_as_half((unsigned short)(hp & 0xffff));
                    g_vt[(size_t)(col + 1) * S_LEN + r] = __ushort_as_half((unsigned short)(hp >> 16));
                }
            }
}

// ---------------------------------------------------------------------------
// Output projection with integrated c-fold + bias adjust:
//   prologue: c[1024] from g_cpart (smem), then badj[128] for this col block
//   Out = Zhi * Wo_hi^T + badj   (fp32 out)
// ---------------------------------------------------------------------------
__global__ __launch_bounds__(256, 2) void gemm_out(
    const float* __restrict__ WOw, const float* __restrict__ WOb, float* __restrict__ ofp)
{
    extern __shared__ char smem[];
    __shared__ float cs[D_MODEL];
    __shared__ float badj_s[128];
    uint32_t sb = smem_u32(smem);
    const int row0 = blockIdx.y << 7, col0 = blockIdx.x << 7;
    const int tid = threadIdx.x, lane = tid & 31, wid = tid >> 5;

    // fold segment partials into c (same seg order as before -> bit-identical)
    for (int j = tid; j < D_MODEL; j += 256) {
        const int h = j >> 6, v = j & 63;
        float s = 0.f;
#pragma unroll
        for (int seg = 0; seg < 16; seg++)
            s += g_cpart[(h * 16 + seg) * HDIM + v];
        cs[j] = s;
    }
    __syncthreads();

    // badj for this CTA's 128 columns: 8 warps x 16 cols, lane-strided dot
    for (int cc = wid * 16; cc < wid * 16 + 16; cc++) {
        const float* wr = WOw + (size_t)(col0 + cc) * D_MODEL;
        float s = 0.f;
#pragma unroll 4
        for (int j = lane; j < D_MODEL; j += 32)
            s = fmaf(wr[j], cs[j], s);
#pragma unroll
        for (int o = 16; o > 0; o >>= 1) s += __shfl_xor_sync(0xffffffffu, s, o);
        if (lane == 0) badj_s[cc] = WOb[col0 + cc] - s;
    }
    __syncthreads();

    float acc[2][8][4];
#pragma unroll
    for (int f = 0; f < 2; f++)
#pragma unroll
        for (int j = 0; j < 8; j++)
#pragma unroll
            for (int q = 0; q < 4; q++) acc[f][j][q] = 0.f;

    mma_mainloop128_1p(sb, acc, g_zh, D_MODEL, row0, g_wo, D_MODEL, col0, D_MODEL / 32);

    const int wm = (wid & 3) * 32, wn = (wid >> 2) * 64;
    const int rb = row0 + wm + (lane >> 2);
    const int cl = wn + (lane & 3) * 2;     // column within block [0,128)
#pragma unroll
    for (int f = 0; f < 2; f++)
#pragma unroll
        for (int j = 0; j < 8; j++)
#pragma unroll
            for (int rh = 0; rh < 2; rh++) {
                const int r = rb + f * 16 + rh * 8;
                const int c0 = cl + j * 8;
                *(float2*)(ofp + (size_t)r * D_MODEL + col0 + c0) = make_float2(
                    acc[f][j][rh * 2 + 0] + badj_s[c0],
                    acc[f][j][rh * 2 + 1] + badj_s[c0 + 1]);
            }
}

// ---------------------------------------------------------------------------
// Fused attention, 512 threads = 2 independent warp-groups per CTA.
// ---------------------------------------------------------------------------
#define PQB  144
#define PVB  272
#define QSZ  (128 * PQB)              // 18432
#define VSZ  (64 * PVB)               // 17408
#define OFF_K    QSZ                              // 18432 (K hi, 2 stages)
#define OFF_V    (OFF_K + 2 * QSZ)                // 55296 (V hi, 2 stages)
#define OFF_PART (OFF_V + 2 * VSZ)                // 90112
#define FHALF    (OFF_PART + 8 * 128 * 4)         // 94208 per warp-group
#define FATTN_SMEM (2 * FHALF)                    // 188416

__global__ __launch_bounds__(512) void fused_attn()
{
    extern __shared__ char smem[];
    const int tid512 = threadIdx.x;
    const int wg   = tid512 >> 8;          // warp-group 0/1
    const int tid  = tid512 & 255;         // id within group
    const int lane = tid & 31, wid = tid >> 5;
    const int h = blockIdx.y;
    const int barid = wg + 1;

    uint32_t sb = smem_u32(smem) + (uint32_t)wg * FHALF;
    float* spart = (float*)(smem + wg * FHALF + OFF_PART);

    const int sblk = wg ? (15 - (int)blockIdx.x) : (int)blockIdx.x;
    const int row0 = sblk << 7;
    const int ntb  = sblk + 1;

    const uint32_t qoff = sb + (uint32_t)((wid * 16 + (lane & 15)) * PQB + ((lane & 16) ? 16 : 0));
    const uint32_t kvlane = (uint32_t)((lane & 7) + ((lane & 16) ? 8 : 0));
    const uint32_t koff_l = kvlane * PQB + ((lane & 8) ? 16 : 0);
    const uint32_t voff_l = kvlane * PVB + ((lane & 8) ? 16 : 0);

    // Q tile (hi only)
    for (int i = tid; i < 128 * 8; i += 256) {
        int r = i >> 3, cbyte = (i & 7) << 4;
        cp_async16(sb + (uint32_t)(r * PQB) + cbyte,
                   (const char*)(g_qh + (size_t)(row0 + r) * D_MODEL + h * HDIM) + cbyte);
    }
    cp_commit();

    auto loadKV = [&](int tb) {
        uint32_t kbase = sb + OFF_K + (uint32_t)(tb & 1) * QSZ;
        uint32_t vbase = sb + OFF_V + (uint32_t)(tb & 1) * VSZ;
        const int col0 = tb << 7;
        for (int i = tid; i < 128 * 8; i += 256) {
            int r = i >> 3, cbyte = (i & 7) << 4;
            cp_async16(kbase + (uint32_t)(r * PQB) + cbyte,
                       (const char*)(g_kh + (size_t)(col0 + r) * D_MODEL + h * HDIM) + cbyte);
        }
        for (int i = tid; i < 64 * 16; i += 256) {
            int r = i >> 4, cbyte = (i & 15) << 4;
            cp_async16(vbase + (uint32_t)(r * PVB) + cbyte,
                       (const char*)(g_vt + (size_t)(h * HDIM + r) * S_LEN + col0) + cbyte);
        }
        cp_commit();
    };
    loadKV(0);

    float oacc[8][4];
#pragma unroll
    for (int j = 0; j < 8; j++)
#pragma unroll
        for (int q = 0; q < 4; q++) oacc[j][q] = 0.f;

    for (int tb = 0; tb < ntb; tb++) {
        if (tb + 1 < ntb) { loadKV(tb + 1); cp_wait<1>(); }
        else              { cp_wait<0>(); }
        bar_sync(barid, 256);

        uint32_t kbase = sb + OFF_K + (uint32_t)(tb & 1) * QSZ;
        uint32_t vbase = sb + OFF_V + (uint32_t)(tb & 1) * VSZ;

        const bool diag = (tb == sblk);
        const int pmax  = diag ? (wid + 1) : 8;
        const int nfmax = diag ? (2 * wid + 2) : 16;

        // ---- MMA1: S[16 x 128] per warp, 1-pass ----
        float sacc[16][4];
#pragma unroll
        for (int j = 0; j < 16; j++)
#pragma unroll
            for (int q = 0; q < 4; q++) sacc[j][q] = 0.f;

        const uint32_t koff = kbase + koff_l;
#pragma unroll
        for (int ks = 0; ks < 4; ks++) {
            const uint32_t ko = (uint32_t)(ks * 32);
            uint32_t ah[4];
            LDSM_X4(ah, qoff + ko);
#pragma unroll
            for (int p = 0; p < 8; p++) {
                if (p < pmax) {
                    uint32_t bh[4];
                    LDSM_X4(bh, koff + (uint32_t)(p * 16 * PQB) + ko);
                    mma16816(sacc[2*p],   ah, bh);
                    mma16816(sacc[2*p+1], ah, bh + 2);
                }
            }
        }

        // ---- mask + exp partial column sums (MUFU) ----
        const int r0 = row0 + wid * 16 + (lane >> 2);
        const int r1 = r0 + 8;
        const int cb2 = (tb << 7) + 2 * (lane & 3);
#pragma unroll
        for (int nf = 0; nf < 16; nf++) {
            float eA = 0.f, eB = 0.f;
            if (nf < nfmax) {
                const int c0 = cb2 + nf * 8;
                float s0 = sacc[nf][0], s1 = sacc[nf][1];
                float s2 = sacc[nf][2], s3 = sacc[nf][3];
                bool m0 = true, m1 = true, m2 = true, m3 = true;
                if (diag) {
                    m0 = (c0 <= r0); m1 = (c0 + 1 <= r0);
                    m2 = (c0 <= r1); m3 = (c0 + 1 <= r1);
                    s0 = m0 ? s0 : 0.f; s1 = m1 ? s1 : 0.f;
                    s2 = m2 ? s2 : 0.f; s3 = m3 ? s3 : 0.f;
                    sacc[nf][0] = s0; sacc[nf][1] = s1;
                    sacc[nf][2] = s2; sacc[nf][3] = s3;
                }
                float e0 = __expf(s0), e1 = __expf(s1);
                float e2 = __expf(s2), e3 = __expf(s3);
                if (diag) {
                    e0 = m0 ? e0 : 0.f; e1 = m1 ? e1 : 0.f;
                    e2 = m2 ? e2 : 0.f; e3 = m3 ? e3 : 0.f;
                }
                eA = e0 + e2; eB = e1 + e3;
                eA += __shfl_xor_sync(0xffffffffu, eA, 4);
                eA += __shfl_xor_sync(0xffffffffu, eA, 8);
                eA += __shfl_xor_sync(0xffffffffu, eA, 16);
                eB += __shfl_xor_sync(0xffffffffu, eB, 4);
                eB += __shfl_xor_sync(0xffffffffu, eB, 8);
                eB += __shfl_xor_sync(0xffffffffu, eB, 16);
            }
            if (lane < 4) {
                spart[wid * 128 + nf * 8 + 2 * lane]     = eA;
                spart[wid * 128 + nf * 8 + 2 * lane + 1] = eB;
            }
        }

        // ---- MMA2: O += S_hi @ V_hi^T, 1-pass ----
        const uint32_t voff = vbase + voff_l;
#pragma unroll
        for (int kc = 0; kc < 8; kc++) {
            if (kc < pmax) {
                uint32_t ahi[4];
                ahi[0] = pack2h(sacc[2*kc][0],   sacc[2*kc][1]);
                ahi[1] = pack2h(sacc[2*kc][2],   sacc[2*kc][3]);
                ahi[2] = pack2h(sacc[2*kc+1][0], sacc[2*kc+1][1]);
                ahi[3] = pack2h(sacc[2*kc+1][2], sacc[2*kc+1][3]);
                const uint32_t ko = (uint32_t)(kc * 32);
#pragma unroll
                for (int p = 0; p < 4; p++) {
                    uint32_t bh[4];
                    LDSM_X4(bh, voff + (uint32_t)(p * 16 * PVB) + ko);
                    mma16816(oacc[2*p],   ahi, bh);
                    mma16816(oacc[2*p+1], ahi, bh + 2);
                }
            }
        }

        bar_sync(barid, 256);
        if (tid < 128) {
            float s = 0.f;
#pragma unroll
            for (int w = 0; w < 8; w++) s += spart[w * 128 + tid];
            g_part[((h * 16 + sblk) << 11) + (tb << 7) + tid] = s;
        }
    }

    // ---- epilogue: Z_hi = fp16(O) ----
    {
        const int r0 = row0 + wid * 16 + (lane >> 2);
        const int cb2 = 2 * (lane & 3);
#pragma unroll
        for (int nf = 0; nf < 8; nf++) {
            const int col = h * HDIM + nf * 8 + cb2;
            *(uint32_t*)(g_zh + (size_t)r0 * D_MODEL + col)       = pack2h(oacc[nf][0], oacc[nf][1]);
            *(uint32_t*)(g_zh + (size_t)(r0 + 8) * D_MODEL + col) = pack2h(oacc[nf][2], oacc[nf][3]);
        }
    }
}

// ---------------------------------------------------------------------------
// Parallel L + partial c: grid(16 segs, 16 heads), 256 threads.
// ---------------------------------------------------------------------------
__global__ __launch_bounds__(256) void lse_c_part()
{
    __shared__ float Ls[128];
    __shared__ float part[4][HDIM];
    const int seg = blockIdx.x, h = blockIdx.y;
    const int tid = threadIdx.x;

    if (tid < 128) {
        const int t = (seg << 7) + tid;
        float acc = (float)t;
        for (int sbk = seg; sbk < 16; sbk++)
            acc += g_part[((h * 16 + sbk) << 11) + t];
        Ls[tid] = logf(acc);
    }
    __syncthreads();

    const int v = tid & 63;
    const int g = tid >> 6;
    const __half2* th = (const __half2*)(g_vt + (size_t)(h * HDIM + v) * S_LEN
                                         + (seg << 7) + (g << 5));
    const float* lp = Ls + (g << 5);
    float s0 = 0.f, s1 = 0.f;
#pragma unroll
    for (int i = 0; i < 16; i++) {
        float2 hv = __half22float2(th[i]);
        s0 = fmaf(lp[2 * i],     hv.x, s0);
        s1 = fmaf(lp[2 * i + 1], hv.y, s1);
    }
    part[g][v] = s0 + s1;
    __syncthreads();
    if (g == 0)
        g_cpart[(h * 16 + seg) * HDIM + v] =
            (part[0][v] + part[1][v]) + (part[2][v] + part[3][v]);
}

// ---------------------------------------------------------------------------
// One-shot fp32 -> fp16 conversion: 3 inputs + 4 weights, hi only.
// ---------------------------------------------------------------------------
__global__ __launch_bounds__(256) void split_all(
    const float4* __restrict__ Qin, const float4* __restrict__ Kin, const float4* __restrict__ Vin,
    const float4* __restrict__ WQw, const float4* __restrict__ WKw,
    const float4* __restrict__ WVw, const float4* __restrict__ WOw)
{
    const int b = blockIdx.x;
    const float4* src;
    uint4* hi;
    int rb;
    if (b < 3072) {
        const int t = b >> 10; rb = b & 1023;
        src = (t == 0) ? Qin : (t == 1) ? Kin : Vin;
        hi = (uint4*)((t == 0) ? g_iq : (t == 1) ? g_ik : g_iv);
    } else {
        const int bb = b - 3072, t = bb >> 9; rb = bb & 511;
        src = (t == 0) ? WQw : (t == 1) ? WKw : (t == 2) ? WVw : WOw;
        hi = (uint4*)((t == 0) ? g_wq : (t == 1) ? g_wk : (t == 2) ? g_wv : g_wo);
    }
    const int i = rb * 256 + threadIdx.x;
    float4 a = src[2 * i], c = src[2 * i + 1];
    hi[i] = make_uint4(pack2h(a.x, a.y), pack2h(a.z, a.w),
                       pack2h(c.x, c.y), pack2h(c.z, c.w));
}

// ---------------------------------------------------------------------------
extern "C" void kernel_launch(void* const* d_in, const int* in_sizes, int n_in,
                              void* d_out, int out_size)
{
    const float* Qin = (const float*)d_in[0];
    const float* Kin = (const float*)d_in[1];
    const float* Vin = (const float*)d_in[2];
    const float* WQw = (const float*)d_in[3];
    const float* WQb = (const float*)d_in[4];
    const float* WKw = (const float*)d_in[5];
    const float* WKb = (const float*)d_in[6];
    const float* WVw = (const float*)d_in[7];
    const float* WVb = (const float*)d_in[8];
    const float* WOw = (const float*)d_in[9];
    const float* WOb = (const float*)d_in[10];
    float* Out = (float*)d_out;

    cudaFuncSetAttribute(gemm_qkv,   cudaFuncAttributeMaxDynamicSharedMemorySize, SMEM_PROJ);
    cudaFuncSetAttribute(gemm_out,   cudaFuncAttributeMaxDynamicSharedMemorySize, SMEM_PROJ);
    cudaFuncSetAttribute(fused_attn, cudaFuncAttributeMaxDynamicSharedMemorySize, FATTN_SMEM);

    dim3 blk(256);

    // 1) fp16 conversions
    split_all<<<5120, blk>>>((const float4*)Qin, (const float4*)Kin, (const float4*)Vin,
                             (const float4*)WQw, (const float4*)WKw,
                             (const float4*)WVw, (const float4*)WOw);

    // 2) Q/K/V projections
    dim3 gqkv(D_MODEL / 128, S_LEN / 128, 3);
    gemm_qkv<<<gqkv, blk, SMEM_PROJ>>>(WQb, WKb, WVb);

    // 3) fused attention (512 threads, 2 concurrent warp-groups)
    dim3 gfa(8, NHEAD);
    fused_attn<<<gfa, dim3(512), FATTN_SMEM>>>();

    // 4) parallel L + partial c (256 CTAs)
    dim3 glc(16, NHEAD);
    lse_c_part<<<glc, blk>>>();

    // 5) output projection with integrated c-fold + bias adjust
    dim3 gout(D_MODEL / 128, S_LEN / 128);
    gemm_out<<<gout, blk, SMEM_PROJ>>>(WOw, WOb, Out);
}

// round 16
// speedup vs baseline: 1.2240x; 1.2240x over previous
#include <cuda_runtime.h>
#include <cuda_fp16.h>
#include <stdint.h>
#include <math.h>

#define S_LEN   2048
#define D_MODEL 1024
#define NHEAD   16
#define HDIM    64

typedef __half fp16;

// ---------------------------------------------------------------------------
// Device-global scratch (allocation-free, zero-init at load).
// ---------------------------------------------------------------------------
static __device__ fp16  g_iq[S_LEN * D_MODEL], g_ik[S_LEN * D_MODEL], g_iv[S_LEN * D_MODEL];
static __device__ fp16  g_wq[D_MODEL * D_MODEL], g_wk[D_MODEL * D_MODEL];
static __device__ fp16  g_wv[D_MODEL * D_MODEL], g_wo[D_MODEL * D_MODEL];
static __device__ fp16  g_qh[S_LEN * D_MODEL];                          // q hi, pre-scaled 0.125
static __device__ fp16  g_kh[S_LEN * D_MODEL];                          // k hi
static __device__ fp16  g_vt[D_MODEL * S_LEN];                          // V^T hi [h*64+v][t]
static __device__ fp16  g_zh[S_LEN * D_MODEL];                          // Z hi
static __device__ float g_part[NHEAD * 16 * S_LEN];
static __device__ float g_cpart[NHEAD * 16 * HDIM];                     // [h][seg][v]
static __device__ float g_badj[D_MODEL];

// ---------------------------------------------------------------------------
// PTX helpers (generic sm_80-class PTX, legal under compute_103)
// ---------------------------------------------------------------------------
__device__ __forceinline__ uint32_t smem_u32(const void* p) {
    uint32_t a;
    asm("{ .reg .u64 t; cvta.to.shared.u64 t, %1; cvt.u32.u64 %0, t; }" : "=r"(a) : "l"(p));
    return a;
}
__device__ __forceinline__ void cp_async16(uint32_t dst, const void* src) {
    asm volatile("cp.async.cg.shared.global [%0], [%1], 16;" :: "r"(dst), "l"(src));
}
__device__ __forceinline__ void cp_commit() {
    asm volatile("cp.async.commit_group;" ::: "memory");
}
template<int N> __device__ __forceinline__ void cp_wait() {
    asm volatile("cp.async.wait_group %0;" :: "n"(N) : "memory");
}
__device__ __forceinline__ void bar_sync(int id, int cnt) {
    asm volatile("bar.sync %0, %1;" :: "r"(id), "r"(cnt) : "memory");
}

#define LDSM_X4(r, addr) \
    asm volatile("ldmatrix.sync.aligned.m8n8.x4.shared.b16 {%0,%1,%2,%3}, [%4];" \
        : "=r"((r)[0]), "=r"((r)[1]), "=r"((r)[2]), "=r"((r)[3]) : "r"(addr))

__device__ __forceinline__ void mma16816(float* c, const uint32_t* a, const uint32_t* b) {
    asm volatile(
        "mma.sync.aligned.m16n8k16.row.col.f32.f16.f16.f32 "
        "{%0,%1,%2,%3}, {%4,%5,%6,%7}, {%8,%9}, {%0,%1,%2,%3};"
        : "+f"(c[0]), "+f"(c[1]), "+f"(c[2]), "+f"(c[3])
        : "r"(a[0]), "r"(a[1]), "r"(a[2]), "r"(a[3]), "r"(b[0]), "r"(b[1]));
}

__device__ __forceinline__ uint32_t pack2h(float v0, float v1) {
    uint32_t r;
    asm("cvt.rn.f16x2.f32 %0, %1, %2;" : "=r"(r) : "f"(v1), "f"(v0));
    return r;
}

// ---------------------------------------------------------------------------
// 1-pass GEMM mainloop: 128x128 tile, BK=32, 3-stage cp.async pipeline.
// ---------------------------------------------------------------------------
#define PITCHB 80
#define AB128 (128 * PITCHB)
#define STAGE1 (2 * AB128)             // 20480
#define SMEM_PROJ (3 * STAGE1)         // 61440

__device__ __forceinline__ void mma_mainloop128_1p(
    uint32_t sb, float (&acc)[2][8][4],
    const fp16* __restrict__ Ahi, int lda, int arow0,
    const fp16* __restrict__ Bhi, int ldb, int brow0,
    int nchunks)
{
    const int tid = threadIdx.x, lane = tid & 31, wid = tid >> 5;
    const int wm = (wid & 3) * 32, wn = (wid >> 2) * 64;

    auto load = [&](int c) {
        uint32_t s = sb + (uint32_t)(c % 3) * STAGE1;
        const int k0 = c * 32;
        for (int i = tid; i < 128 * 4; i += 256) {
            int r = i >> 2, cb = (i & 3) << 4;
            cp_async16(s + (uint32_t)(r * PITCHB + cb),
                       (const char*)(Ahi + (size_t)(arow0 + r) * lda + k0) + cb);
            cp_async16(s + AB128 + (uint32_t)(r * PITCHB + cb),
                       (const char*)(Bhi + (size_t)(brow0 + r) * ldb + k0) + cb);
        }
        cp_commit();
    };

    const uint32_t aoff = (uint32_t)((wm + (lane & 15)) * PITCHB + ((lane & 16) ? 16 : 0));
    const uint32_t boff = (uint32_t)((wn + (lane & 7) + ((lane & 16) ? 8 : 0)) * PITCHB +
                                     ((lane & 8) ? 16 : 0));

    load(0);
    if (nchunks > 1) load(1);
    for (int c = 0; c < nchunks; c++) {
        if (c + 2 < nchunks) { load(c + 2); cp_wait<2>(); }
        else if (c + 1 < nchunks) cp_wait<1>();
        else cp_wait<0>();
        __syncthreads();
        uint32_t s  = sb + (uint32_t)(c % 3) * STAGE1;
        uint32_t sa = s + aoff;
        uint32_t sbb = s + AB128 + boff;
#pragma unroll
        for (int ks = 0; ks < 2; ks++) {
            const uint32_t ko = (uint32_t)(ks * 32);
            uint32_t ah[2][4];
            LDSM_X4(ah[0], sa + ko);
            LDSM_X4(ah[1], sa + 16 * PITCHB + ko);
            uint32_t bh[8][2];
#pragma unroll
            for (int p = 0; p < 4; p++) {
                uint32_t r4[4];
                LDSM_X4(r4, sbb + (uint32_t)(p * 16 * PITCHB) + ko);
                bh[2*p][0] = r4[0]; bh[2*p][1] = r4[1];
                bh[2*p+1][0] = r4[2]; bh[2*p+1][1] = r4[3];
            }
#pragma unroll
            for (int f = 0; f < 2; f++)
#pragma unroll
                for (int j = 0; j < 8; j++)
                    mma16816(acc[f][j], ah[f], bh[j]);
        }
        __syncthreads();
    }
}

// ---------------------------------------------------------------------------
// Merged Q/K/V projections: grid(8, 16, 3). z: 0=Q (scale 0.125), 1=K, 2=V(T).
// ---------------------------------------------------------------------------
__global__ __launch_bounds__(256, 2) void gemm_qkv(
    const float* __restrict__ bq, const float* __restrict__ bk, const float* __restrict__ bv)
{
    extern __shared__ char smem[];
    uint32_t sb = smem_u32(smem);
    const int z = blockIdx.z;
    const int row0 = blockIdx.y << 7, col0 = blockIdx.x << 7;

    const fp16* Ah = (z == 0) ? g_iq : (z == 1) ? g_ik : g_iv;
    const fp16* Bh = (z == 0) ? g_wq : (z == 1) ? g_wk : g_wv;
    const float* bias = (z == 0) ? bq : (z == 1) ? bk : bv;
    const float scale = (z == 0) ? 0.125f : 1.0f;

    float acc[2][8][4];
#pragma unroll
    for (int f = 0; f < 2; f++)
#pragma unroll
        for (int j = 0; j < 8; j++)
#pragma unroll
            for (int q = 0; q < 4; q++) acc[f][j][q] = 0.f;

    mma_mainloop128_1p(sb, acc, Ah, D_MODEL, row0, Bh, D_MODEL, col0, D_MODEL / 32);

    const int lane = threadIdx.x & 31, wid = threadIdx.x >> 5;
    const int wm = (wid & 3) * 32, wn = (wid >> 2) * 64;
    const int rb = row0 + wm + (lane >> 2);
    const int cb = col0 + wn + (lane & 3) * 2;
    fp16* ohi = (z == 0) ? g_qh : g_kh;
#pragma unroll
    for (int f = 0; f < 2; f++)
#pragma unroll
        for (int j = 0; j < 8; j++)
#pragma unroll
            for (int rh = 0; rh < 2; rh++) {
                const int r = rb + f * 16 + rh * 8;
                const int col = cb + j * 8;
                float v0 = (acc[f][j][rh * 2 + 0] + bias[col])     * scale;
                float v1 = (acc[f][j][rh * 2 + 1] + bias[col + 1]) * scale;
                uint32_t hp = pack2h(v0, v1);
                if (z < 2) {
                    *(uint32_t*)(ohi + (size_t)r * D_MODEL + col) = hp;
                } else {
                    g_vt[(size_t)col * S_LEN + r]       = __ushort_as_half((unsigned short)(hp & 0xffff));
                    g_vt[(size_t)(col + 1) * S_LEN + r] = __ushort_as_half((unsigned short)(hp >> 16));
                }
            }
}

// ---------------------------------------------------------------------------
// Output projection: Out = Zhi * Wo_hi^T + badj  (fp32 out)
// ---------------------------------------------------------------------------
__global__ __launch_bounds__(256, 2) void gemm_out(float* __restrict__ ofp)
{
    extern __shared__ char smem[];
    uint32_t sb = smem_u32(smem);
    const int row0 = blockIdx.y << 7, col0 = blockIdx.x << 7;
    float acc[2][8][4];
#pragma unroll
    for (int f = 0; f < 2; f++)
#pragma unroll
        for (int j = 0; j < 8; j++)
#pragma unroll
            for (int q = 0; q < 4; q++) acc[f][j][q] = 0.f;

    mma_mainloop128_1p(sb, acc, g_zh, D_MODEL, row0, g_wo, D_MODEL, col0, D_MODEL / 32);

    const int lane = threadIdx.x & 31, wid = threadIdx.x >> 5;
    const int wm = (wid & 3) * 32, wn = (wid >> 2) * 64;
    const int rb = row0 + wm + (lane >> 2);
    const int cb = col0 + wn + (lane & 3) * 2;
#pragma unroll
    for (int f = 0; f < 2; f++)
#pragma unroll
        for (int j = 0; j < 8; j++)
#pragma unroll
            for (int rh = 0; rh < 2; rh++) {
                const int r = rb + f * 16 + rh * 8;
                const int col = cb + j * 8;
                *(float2*)(ofp + (size_t)r * D_MODEL + col) = make_float2(
                    acc[f][j][rh * 2 + 0] + g_badj[col],
                    acc[f][j][rh * 2 + 1] + g_badj[col + 1]);
            }
}

// ---------------------------------------------------------------------------
// Fused attention, 512 threads = 2 independent warp-groups per CTA.
// ---------------------------------------------------------------------------
#define PQB  144
#define PVB  272
#define QSZ  (128 * PQB)              // 18432
#define VSZ  (64 * PVB)               // 17408
#define OFF_K    QSZ                              // 18432 (K hi, 2 stages)
#define OFF_V    (OFF_K + 2 * QSZ)                // 55296 (V hi, 2 stages)
#define OFF_PART (OFF_V + 2 * VSZ)                // 90112
#define FHALF    (OFF_PART + 8 * 128 * 4)         // 94208 per warp-group
#define FATTN_SMEM (2 * FHALF)                    // 188416

__global__ __launch_bounds__(512) void fused_attn()
{
    extern __shared__ char smem[];
    const int tid512 = threadIdx.x;
    const int wg   = tid512 >> 8;          // warp-group 0/1
    const int tid  = tid512 & 255;         // id within group
    const int lane = tid & 31, wid = tid >> 5;
    const int h = blockIdx.y;
    const int barid = wg + 1;

    uint32_t sb = smem_u32(smem) + (uint32_t)wg * FHALF;
    float* spart = (float*)(smem + wg * FHALF + OFF_PART);

    const int sblk = wg ? (15 - (int)blockIdx.x) : (int)blockIdx.x;
    const int row0 = sblk << 7;
    const int ntb  = sblk + 1;

    const uint32_t qoff = sb + (uint32_t)((wid * 16 + (lane & 15)) * PQB + ((lane & 16) ? 16 : 0));
    const uint32_t kvlane = (uint32_t)((lane & 7) + ((lane & 16) ? 8 : 0));
    const uint32_t koff_l = kvlane * PQB + ((lane & 8) ? 16 : 0);
    const uint32_t voff_l = kvlane * PVB + ((lane & 8) ? 16 : 0);

    // Q tile (hi only)
    for (int i = tid; i < 128 * 8; i += 256) {
        int r = i >> 3, cbyte = (i & 7) << 4;
        cp_async16(sb + (uint32_t)(r * PQB) + cbyte,
                   (const char*)(g_qh + (size_t)(row0 + r) * D_MODEL + h * HDIM) + cbyte);
    }
    cp_commit();

    auto loadKV = [&](int tb) {
        uint32_t kbase = sb + OFF_K + (uint32_t)(tb & 1) * QSZ;
        uint32_t vbase = sb + OFF_V + (uint32_t)(tb & 1) * VSZ;
        const int col0 = tb << 7;
        for (int i = tid; i < 128 * 8; i += 256) {
            int r = i >> 3, cbyte = (i & 7) << 4;
            cp_async16(kbase + (uint32_t)(r * PQB) + cbyte,
                       (const char*)(g_kh + (size_t)(col0 + r) * D_MODEL + h * HDIM) + cbyte);
        }
        for (int i = tid; i < 64 * 16; i += 256) {
            int r = i >> 4, cbyte = (i & 15) << 4;
            cp_async16(vbase + (uint32_t)(r * PVB) + cbyte,
                       (const char*)(g_vt + (size_t)(h * HDIM + r) * S_LEN + col0) + cbyte);
        }
        cp_commit();
    };
    loadKV(0);

    float oacc[8][4];
#pragma unroll
    for (int j = 0; j < 8; j++)
#pragma unroll
        for (int q = 0; q < 4; q++) oacc[j][q] = 0.f;

    for (int tb = 0; tb < ntb; tb++) {
        if (tb + 1 < ntb) { loadKV(tb + 1); cp_wait<1>(); }
        else              { cp_wait<0>(); }
        bar_sync(barid, 256);

        uint32_t kbase = sb + OFF_K + (uint32_t)(tb & 1) * QSZ;
        uint32_t vbase = sb + OFF_V + (uint32_t)(tb & 1) * VSZ;

        const bool diag = (tb == sblk);
        const int pmax  = diag ? (wid + 1) : 8;
        const int nfmax = diag ? (2 * wid + 2) : 16;

        // ---- MMA1: S[16 x 128] per warp, 1-pass ----
        float sacc[16][4];
#pragma unroll
        for (int j = 0; j < 16; j++)
#pragma unroll
            for (int q = 0; q < 4; q++) sacc[j][q] = 0.f;

        const uint32_t koff = kbase + koff_l;
#pragma unroll
        for (int ks = 0; ks < 4; ks++) {
            const uint32_t ko = (uint32_t)(ks * 32);
            uint32_t ah[4];
            LDSM_X4(ah, qoff + ko);
#pragma unroll
            for (int p = 0; p < 8; p++) {
                if (p < pmax) {
                    uint32_t bh[4];
                    LDSM_X4(bh, koff + (uint32_t)(p * 16 * PQB) + ko);
                    mma16816(sacc[2*p],   ah, bh);
                    mma16816(sacc[2*p+1], ah, bh + 2);
                }
            }
        }

        // ---- mask + exp partial column sums (MUFU) ----
        const int r0 = row0 + wid * 16 + (lane >> 2);
        const int r1 = r0 + 8;
        const int cb2 = (tb << 7) + 2 * (lane & 3);
#pragma unroll
        for (int nf = 0; nf < 16; nf++) {
            float eA = 0.f, eB = 0.f;
            if (nf < nfmax) {
                const int c0 = cb2 + nf * 8;
                float s0 = sacc[nf][0], s1 = sacc[nf][1];
                float s2 = sacc[nf][2], s3 = sacc[nf][3];
                bool m0 = true, m1 = true, m2 = true, m3 = true;
                if (diag) {
                    m0 = (c0 <= r0); m1 = (c0 + 1 <= r0);
                    m2 = (c0 <= r1); m3 = (c0 + 1 <= r1);
                    s0 = m0 ? s0 : 0.f; s1 = m1 ? s1 : 0.f;
                    s2 = m2 ? s2 : 0.f; s3 = m3 ? s3 : 0.f;
                    sacc[nf][0] = s0; sacc[nf][1] = s1;
                    sacc[nf][2] = s2; sacc[nf][3] = s3;
                }
                float e0 = __expf(s0), e1 = __expf(s1);
                float e2 = __expf(s2), e3 = __expf(s3);
                if (diag) {
                    e0 = m0 ? e0 : 0.f; e1 = m1 ? e1 : 0.f;
                    e2 = m2 ? e2 : 0.f; e3 = m3 ? e3 : 0.f;
                }
                eA = e0 + e2; eB = e1 + e3;
                eA += __shfl_xor_sync(0xffffffffu, eA, 4);
                eA += __shfl_xor_sync(0xffffffffu, eA, 8);
                eA += __shfl_xor_sync(0xffffffffu, eA, 16);
                eB += __shfl_xor_sync(0xffffffffu, eB, 4);
                eB += __shfl_xor_sync(0xffffffffu, eB, 8);
                eB += __shfl_xor_sync(0xffffffffu, eB, 16);
            }
            if (lane < 4) {
                spart[wid * 128 + nf * 8 + 2 * lane]     = eA;
                spart[wid * 128 + nf * 8 + 2 * lane + 1] = eB;
            }
        }

        // ---- MMA2: O += S_hi @ V_hi^T, 1-pass ----
        const uint32_t voff = vbase + voff_l;
#pragma unroll
        for (int kc = 0; kc < 8; kc++) {
            if (kc < pmax) {
                uint32_t ahi[4];
                ahi[0] = pack2h(sacc[2*kc][0],   sacc[2*kc][1]);
                ahi[1] = pack2h(sacc[2*kc][2],   sacc[2*kc][3]);
                ahi[2] = pack2h(sacc[2*kc+1][0], sacc[2*kc+1][1]);
                ahi[3] = pack2h(sacc[2*kc+1][2], sacc[2*kc+1][3]);
                const uint32_t ko = (uint32_t)(kc * 32);
#pragma unroll
                for (int p = 0; p < 4; p++) {
                    uint32_t bh[4];
                    LDSM_X4(bh, voff + (uint32_t)(p * 16 * PVB) + ko);
                    mma16816(oacc[2*p],   ahi, bh);
                    mma16816(oacc[2*p+1], ahi, bh + 2);
                }
            }
        }

        bar_sync(barid, 256);
        if (tid < 128) {
            float s = 0.f;
#pragma unroll
            for (int w = 0; w < 8; w++) s += spart[w * 128 + tid];
            g_part[((h * 16 + sblk) << 11) + (tb << 7) + tid] = s;
        }
    }

    // ---- epilogue: Z_hi = fp16(O) ----
    {
        const int r0 = row0 + wid * 16 + (lane >> 2);
        const int cb2 = 2 * (lane & 3);
#pragma unroll
        for (int nf = 0; nf < 8; nf++) {
            const int col = h * HDIM + nf * 8 + cb2;
            *(uint32_t*)(g_zh + (size_t)r0 * D_MODEL + col)       = pack2h(oacc[nf][0], oacc[nf][1]);
            *(uint32_t*)(g_zh + (size_t)(r0 + 8) * D_MODEL + col) = pack2h(oacc[nf][2], oacc[nf][3]);
        }
    }
}

// ---------------------------------------------------------------------------
// Parallel L + partial c: grid(16 segs, 16 heads), 256 threads.
// ---------------------------------------------------------------------------
__global__ __launch_bounds__(256) void lse_c_part()
{
    __shared__ float Ls[128];
    __shared__ float part[4][HDIM];
    const int seg = blockIdx.x, h = blockIdx.y;
    const int tid = threadIdx.x;

    if (tid < 128) {
        const int t = (seg << 7) + tid;
        float acc = (float)t;
        for (int sbk = seg; sbk < 16; sbk++)
            acc += g_part[((h * 16 + sbk) << 11) + t];
        Ls[tid] = logf(acc);
    }
    __syncthreads();

    const int v = tid & 63;
    const int g = tid >> 6;
    const __half2* th = (const __half2*)(g_vt + (size_t)(h * HDIM + v) * S_LEN
                                         + (seg << 7) + (g << 5));
    const float* lp = Ls + (g << 5);
    float s0 = 0.f, s1 = 0.f;
#pragma unroll
    for (int i = 0; i < 16; i++) {
        float2 hv = __half22float2(th[i]);
        s0 = fmaf(lp[2 * i],     hv.x, s0);
        s1 = fmaf(lp[2 * i + 1], hv.y, s1);
    }
    part[g][v] = s0 + s1;
    __syncthreads();
    if (g == 0)
        g_cpart[(h * 16 + seg) * HDIM + v] =
            (part[0][v] + part[1][v]) + (part[2][v] + part[3][v]);
}

// ---------------------------------------------------------------------------
// Merged fold + bias adjust: each CTA folds g_cpart into smem cs[1024]
// (same seg order -> bit-identical c), then 8 warps each compute one row dot.
// grid(128) x 256.
// ---------------------------------------------------------------------------
__global__ __launch_bounds__(256) void bias_adjust(
    const float* __restrict__ WOw, const float* __restrict__ WOb)
{
    __shared__ float cs[D_MODEL];
    const int tid = threadIdx.x, lane = tid & 31, wid = tid >> 5;

    for (int j = tid; j < D_MODEL; j += 256) {
        const int h = j >> 6, v = j & 63;
        float s = 0.f;
#pragma unroll
        for (int seg = 0; seg < 16; seg++)
            s += g_cpart[(h * 16 + seg) * HDIM + v];
        cs[j] = s;
    }
    __syncthreads();

    const int row = blockIdx.x * 8 + wid;
    const float* wr = WOw + (size_t)row * D_MODEL;
    float s = 0.f;
    for (int j = lane; j < D_MODEL; j += 32)
        s = fmaf(wr[j], cs[j], s);
#pragma unroll
    for (int o = 16; o > 0; o >>= 1) s += __shfl_xor_sync(0xffffffffu, s, o);
    if (lane == 0) g_badj[row] = WOb[row] - s;
}

// ---------------------------------------------------------------------------
// One-shot fp32 -> fp16 conversion: 3 inputs + 4 weights, hi only.
// ---------------------------------------------------------------------------
__global__ __launch_bounds__(256) void split_all(
    const float4* __restrict__ Qin, const float4* __restrict__ Kin, const float4* __restrict__ Vin,
    const float4* __restrict__ WQw, const float4* __restrict__ WKw,
    const float4* __restrict__ WVw, const float4* __restrict__ WOw)
{
    const int b = blockIdx.x;
    const float4* src;
    uint4* hi;
    int rb;
    if (b < 3072) {
        const int t = b >> 10; rb = b & 1023;
        src = (t == 0) ? Qin : (t == 1) ? Kin : Vin;
        hi = (uint4*)((t == 0) ? g_iq : (t == 1) ? g_ik : g_iv);
    } else {
        const int bb = b - 3072, t = bb >> 9; rb = bb & 511;
        src = (t == 0) ? WQw : (t == 1) ? WKw : (t == 2) ? WVw : WOw;
        hi = (uint4*)((t == 0) ? g_wq : (t == 1) ? g_wk : (t == 2) ? g_wv : g_wo);
    }
    const int i = rb * 256 + threadIdx.x;
    float4 a = src[2 * i], c = src[2 * i + 1];
    hi[i] = make_uint4(pack2h(a.x, a.y), pack2h(a.z, a.w),
                       pack2h(c.x, c.y), pack2h(c.z, c.w));
}

// ---------------------------------------------------------------------------
extern "C" void kernel_launch(void* const* d_in, const int* in_sizes, int n_in,
                              void* d_out, int out_size)
{
    const float* Qin = (const float*)d_in[0];
    const float* Kin = (const float*)d_in[1];
    const float* Vin = (const float*)d_in[2];
    const float* WQw = (const float*)d_in[3];
    const float* WQb = (const float*)d_in[4];
    const float* WKw = (const float*)d_in[5];
    const float* WKb = (const float*)d_in[6];
    const float* WVw = (const float*)d_in[7];
    const float* WVb = (const float*)d_in[8];
    const float* WOw = (const float*)d_in[9];
    const float* WOb = (const float*)d_in[10];
    float* Out = (float*)d_out;

    cudaFuncSetAttribute(gemm_qkv,   cudaFuncAttributeMaxDynamicSharedMemorySize, SMEM_PROJ);
    cudaFuncSetAttribute(gemm_out,   cudaFuncAttributeMaxDynamicSharedMemorySize, SMEM_PROJ);
    cudaFuncSetAttribute(fused_attn, cudaFuncAttributeMaxDynamicSharedMemorySize, FATTN_SMEM);

    dim3 blk(256);

    // 1) fp16 conversions
    split_all<<<5120, blk>>>((const float4*)Qin, (const float4*)Kin, (const float4*)Vin,
                             (const float4*)WQw, (const float4*)WKw,
                             (const float4*)WVw, (const float4*)WOw);

    // 2) Q/K/V projections
    dim3 gqkv(D_MODEL / 128, S_LEN / 128, 3);
    gemm_qkv<<<gqkv, blk, SMEM_PROJ>>>(WQb, WKb, WVb);

    // 3) fused attention (512 threads, 2 concurrent warp-groups)
    dim3 gfa(8, NHEAD);
    fused_attn<<<gfa, dim3(512), FATTN_SMEM>>>();

    // 4) parallel L + partial c, then merged fold+bias
    dim3 glc(16, NHEAD);
    lse_c_part<<<glc, blk>>>();
    bias_adjust<<<128, blk>>>(WOw, WOb);

    // 5) output projection with folded bias
    dim3 gout(D_MODEL / 128, S_LEN / 128);
    gemm_out<<<gout, blk, SMEM_PROJ>>>(Out);
}

// round 17
// speedup vs baseline: 1.2351x; 1.0091x over previous
#include <cuda_runtime.h>
#include <cuda_fp16.h>
#include <stdint.h>
#include <math.h>

#define S_LEN   2048
#define D_MODEL 1024
#define NHEAD   16
#define HDIM    64

typedef __half fp16;

// ---------------------------------------------------------------------------
// Device-global scratch (allocation-free, zero-init at load).
// ---------------------------------------------------------------------------
static __device__ fp16  g_iq[S_LEN * D_MODEL], g_ik[S_LEN * D_MODEL], g_iv[S_LEN * D_MODEL];
static __device__ fp16  g_wq[D_MODEL * D_MODEL], g_wk[D_MODEL * D_MODEL];
static __device__ fp16  g_wv[D_MODEL * D_MODEL], g_wo[D_MODEL * D_MODEL];
static __device__ fp16  g_qh[S_LEN * D_MODEL];                          // q hi, pre-scaled 0.125
static __device__ fp16  g_kh[S_LEN * D_MODEL];                          // k hi
static __device__ fp16  g_vt[D_MODEL * S_LEN];                          // V^T hi [h*64+v][t]
static __device__ fp16  g_zh[S_LEN * D_MODEL];                          // Z hi
static __device__ float g_part[NHEAD * 16 * S_LEN];
static __device__ float g_cpart[NHEAD * 16 * HDIM];                     // [h][seg][v]
static __device__ float g_badj[D_MODEL];

// ---------------------------------------------------------------------------
// PTX helpers (generic sm_80-class PTX, legal under compute_103)
// ---------------------------------------------------------------------------
__device__ __forceinline__ uint32_t smem_u32(const void* p) {
    uint32_t a;
    asm("{ .reg .u64 t; cvta.to.shared.u64 t, %1; cvt.u32.u64 %0, t; }" : "=r"(a) : "l"(p));
    return a;
}
__device__ __forceinline__ void cp_async16(uint32_t dst, const void* src) {
    asm volatile("cp.async.cg.shared.global [%0], [%1], 16;" :: "r"(dst), "l"(src));
}
__device__ __forceinline__ void cp_commit() {
    asm volatile("cp.async.commit_group;" ::: "memory");
}
template<int N> __device__ __forceinline__ void cp_wait() {
    asm volatile("cp.async.wait_group %0;" :: "n"(N) : "memory");
}
__device__ __forceinline__ void bar_sync(int id, int cnt) {
    asm volatile("bar.sync %0, %1;" :: "r"(id), "r"(cnt) : "memory");
}

#define LDSM_X4(r, addr) \
    asm volatile("ldmatrix.sync.aligned.m8n8.x4.shared.b16 {%0,%1,%2,%3}, [%4];" \
        : "=r"((r)[0]), "=r"((r)[1]), "=r"((r)[2]), "=r"((r)[3]) : "r"(addr))

__device__ __forceinline__ void mma16816(float* c, const uint32_t* a, const uint32_t* b) {
    asm volatile(
        "mma.sync.aligned.m16n8k16.row.col.f32.f16.f16.f32 "
        "{%0,%1,%2,%3}, {%4,%5,%6,%7}, {%8,%9}, {%0,%1,%2,%3};"
        : "+f"(c[0]), "+f"(c[1]), "+f"(c[2]), "+f"(c[3])
        : "r"(a[0]), "r"(a[1]), "r"(a[2]), "r"(a[3]), "r"(b[0]), "r"(b[1]));
}

__device__ __forceinline__ uint32_t pack2h(float v0, float v1) {
    uint32_t r;
    asm("cvt.rn.f16x2.f32 %0, %1, %2;" : "=r"(r) : "f"(v1), "f"(v0));
    return r;
}

// ---------------------------------------------------------------------------
// 1-pass GEMM mainloop: 128x128 tile, BK=32, 3-stage cp.async pipeline.
// ---------------------------------------------------------------------------
#define PITCHB 80
#define AB128 (128 * PITCHB)
#define STAGE1 (2 * AB128)             // 20480
#define SMEM_PROJ (3 * STAGE1)         // 61440

__device__ __forceinline__ void mma_mainloop128_1p(
    uint32_t sb, float (&acc)[2][8][4],
    const fp16* __restrict__ Ahi, int lda, int arow0,
    const fp16* __restrict__ Bhi, int ldb, int brow0,
    int nchunks)
{
    const int tid = threadIdx.x, lane = tid & 31, wid = tid >> 5;
    const int wm = (wid & 3) * 32, wn = (wid >> 2) * 64;

    auto load = [&](int c) {
        uint32_t s = sb + (uint32_t)(c % 3) * STAGE1;
        const int k0 = c * 32;
        for (int i = tid; i < 128 * 4; i += 256) {
            int r = i >> 2, cb = (i & 3) << 4;
            cp_async16(s + (uint32_t)(r * PITCHB + cb),
                       (const char*)(Ahi + (size_t)(arow0 + r) * lda + k0) + cb);
            cp_async16(s + AB128 + (uint32_t)(r * PITCHB + cb),
                       (const char*)(Bhi + (size_t)(brow0 + r) * ldb + k0) + cb);
        }
        cp_commit();
    };

    const uint32_t aoff = (uint32_t)((wm + (lane & 15)) * PITCHB + ((lane & 16) ? 16 : 0));
    const uint32_t boff = (uint32_t)((wn + (lane & 7) + ((lane & 16) ? 8 : 0)) * PITCHB +
                                     ((lane & 8) ? 16 : 0));

    load(0);
    if (nchunks > 1) load(1);
    for (int c = 0; c < nchunks; c++) {
        if (c + 2 < nchunks) { load(c + 2); cp_wait<2>(); }
        else if (c + 1 < nchunks) cp_wait<1>();
        else cp_wait<0>();
        __syncthreads();
        uint32_t s  = sb + (uint32_t)(c % 3) * STAGE1;
        uint32_t sa = s + aoff;
        uint32_t sbb = s + AB128 + boff;
#pragma unroll
        for (int ks = 0; ks < 2; ks++) {
            const uint32_t ko = (uint32_t)(ks * 32);
            uint32_t ah[2][4];
            LDSM_X4(ah[0], sa + ko);
            LDSM_X4(ah[1], sa + 16 * PITCHB + ko);
            uint32_t bh[8][2];
#pragma unroll
            for (int p = 0; p < 4; p++) {
                uint32_t r4[4];
                LDSM_X4(r4, sbb + (uint32_t)(p * 16 * PITCHB) + ko);
                bh[2*p][0] = r4[0]; bh[2*p][1] = r4[1];
                bh[2*p+1][0] = r4[2]; bh[2*p+1][1] = r4[3];
            }
#pragma unroll
            for (int f = 0; f < 2; f++)
#pragma unroll
                for (int j = 0; j < 8; j++)
                    mma16816(acc[f][j], ah[f], bh[j]);
        }
        __syncthreads();
    }
}

// ---------------------------------------------------------------------------
// Merged Q/K/V projections: grid(8, 16, 3). z: 0=Q (scale 0.125), 1=K, 2=V(T).
// V output staged transposed in smem, then written coalesced (16B chunks).
// ---------------------------------------------------------------------------
#define TPITCH 136   // fp16 pitch for transpose staging (272 B rows, 16B-aligned)

__global__ __launch_bounds__(256, 2) void gemm_qkv(
    const float* __restrict__ bq, const float* __restrict__ bk, const float* __restrict__ bv)
{
    extern __shared__ char smem[];
    uint32_t sb = smem_u32(smem);
    const int z = blockIdx.z;
    const int row0 = blockIdx.y << 7, col0 = blockIdx.x << 7;

    const fp16* Ah = (z == 0) ? g_iq : (z == 1) ? g_ik : g_iv;
    const fp16* Bh = (z == 0) ? g_wq : (z == 1) ? g_wk : g_wv;
    const float* bias = (z == 0) ? bq : (z == 1) ? bk : bv;
    const float scale = (z == 0) ? 0.125f : 1.0f;

    float acc[2][8][4];
#pragma unroll
    for (int f = 0; f < 2; f++)
#pragma unroll
        for (int j = 0; j < 8; j++)
#pragma unroll
            for (int q = 0; q < 4; q++) acc[f][j][q] = 0.f;

    mma_mainloop128_1p(sb, acc, Ah, D_MODEL, row0, Bh, D_MODEL, col0, D_MODEL / 32);

    const int tid = threadIdx.x;
    const int lane = tid & 31, wid = tid >> 5;
    const int wm = (wid & 3) * 32, wn = (wid >> 2) * 64;
    const int rb = row0 + wm + (lane >> 2);
    const int cb = col0 + wn + (lane & 3) * 2;
    fp16* ohi = (z == 0) ? g_qh : g_kh;
    fp16* ts = (fp16*)smem;        // reuse GEMM smem (free after final barrier)

#pragma unroll
    for (int f = 0; f < 2; f++)
#pragma unroll
        for (int j = 0; j < 8; j++)
#pragma unroll
            for (int rh = 0; rh < 2; rh++) {
                const int r = rb + f * 16 + rh * 8;
                const int col = cb + j * 8;
                float v0 = (acc[f][j][rh * 2 + 0] + bias[col])     * scale;
                float v1 = (acc[f][j][rh * 2 + 1] + bias[col + 1]) * scale;
                uint32_t hp = pack2h(v0, v1);
                if (z < 2) {
                    *(uint32_t*)(ohi + (size_t)r * D_MODEL + col) = hp;
                } else {
                    const int rl = r - row0, cl = col - col0;
                    ts[(cl)     * TPITCH + rl] = __ushort_as_half((unsigned short)(hp & 0xffff));
                    ts[(cl + 1) * TPITCH + rl] = __ushort_as_half((unsigned short)(hp >> 16));
                }
            }

    if (z == 2) {
        __syncthreads();
        // coalesced write-out: 128 cols x 16 chunks of 16B
        for (int idx = tid; idx < 128 * 16; idx += 256) {
            const int cl = idx >> 4, ch = idx & 15;
            uint4 v = *(const uint4*)(ts + cl * TPITCH + ch * 8);
            *(uint4*)(g_vt + (size_t)(col0 + cl) * S_LEN + row0 + ch * 8) = v;
        }
    }
}

// ---------------------------------------------------------------------------
// Output projection: Out = Zhi * Wo_hi^T + badj  (fp32 out)
// ---------------------------------------------------------------------------
__global__ __launch_bounds__(256, 2) void gemm_out(float* __restrict__ ofp)
{
    extern __shared__ char smem[];
    uint32_t sb = smem_u32(smem);
    const int row0 = blockIdx.y << 7, col0 = blockIdx.x << 7;
    float acc[2][8][4];
#pragma unroll
    for (int f = 0; f < 2; f++)
#pragma unroll
        for (int j = 0; j < 8; j++)
#pragma unroll
            for (int q = 0; q < 4; q++) acc[f][j][q] = 0.f;

    mma_mainloop128_1p(sb, acc, g_zh, D_MODEL, row0, g_wo, D_MODEL, col0, D_MODEL / 32);

    const int lane = threadIdx.x & 31, wid = threadIdx.x >> 5;
    const int wm = (wid & 3) * 32, wn = (wid >> 2) * 64;
    const int rb = row0 + wm + (lane >> 2);
    const int cb = col0 + wn + (lane & 3) * 2;
#pragma unroll
    for (int f = 0; f < 2; f++)
#pragma unroll
        for (int j = 0; j < 8; j++)
#pragma unroll
            for (int rh = 0; rh < 2; rh++) {
                const int r = rb + f * 16 + rh * 8;
                const int col = cb + j * 8;
                *(float2*)(ofp + (size_t)r * D_MODEL + col) = make_float2(
                    acc[f][j][rh * 2 + 0] + g_badj[col],
                    acc[f][j][rh * 2 + 1] + g_badj[col + 1]);
            }
}

// ---------------------------------------------------------------------------
// Fused attention, 512 threads = 2 independent warp-groups per CTA.
// ---------------------------------------------------------------------------
#define PQB  144
#define PVB  272
#define QSZ  (128 * PQB)              // 18432
#define VSZ  (64 * PVB)               // 17408
#define OFF_K    QSZ                              // 18432 (K hi, 2 stages)
#define OFF_V    (OFF_K + 2 * QSZ)                // 55296 (V hi, 2 stages)
#define OFF_PART (OFF_V + 2 * VSZ)                // 90112
#define FHALF    (OFF_PART + 8 * 128 * 4)         // 94208 per warp-group
#define FATTN_SMEM (2 * FHALF)                    // 188416

__global__ __launch_bounds__(512) void fused_attn()
{
    extern __shared__ char smem[];
    const int tid512 = threadIdx.x;
    const int wg   = tid512 >> 8;          // warp-group 0/1
    const int tid  = tid512 & 255;         // id within group
    const int lane = tid & 31, wid = tid >> 5;
    const int h = blockIdx.y;
    const int barid = wg + 1;

    uint32_t sb = smem_u32(smem) + (uint32_t)wg * FHALF;
    float* spart = (float*)(smem + wg * FHALF + OFF_PART);

    const int sblk = wg ? (15 - (int)blockIdx.x) : (int)blockIdx.x;
    const int row0 = sblk << 7;
    const int ntb  = sblk + 1;

    const uint32_t qoff = sb + (uint32_t)((wid * 16 + (lane & 15)) * PQB + ((lane & 16) ? 16 : 0));
    const uint32_t kvlane = (uint32_t)((lane & 7) + ((lane & 16) ? 8 : 0));
    const uint32_t koff_l = kvlane * PQB + ((lane & 8) ? 16 : 0);
    const uint32_t voff_l = kvlane * PVB + ((lane & 8) ? 16 : 0);

    // Q tile (hi only)
    for (int i = tid; i < 128 * 8; i += 256) {
        int r = i >> 3, cbyte = (i & 7) << 4;
        cp_async16(sb + (uint32_t)(r * PQB) + cbyte,
                   (const char*)(g_qh + (size_t)(row0 + r) * D_MODEL + h * HDIM) + cbyte);
    }
    cp_commit();

    auto loadKV = [&](int tb) {
        uint32_t kbase = sb + OFF_K + (uint32_t)(tb & 1) * QSZ;
        uint32_t vbase = sb + OFF_V + (uint32_t)(tb & 1) * VSZ;
        const int col0 = tb << 7;
        for (int i = tid; i < 128 * 8; i += 256) {
            int r = i >> 3, cbyte = (i & 7) << 4;
            cp_async16(kbase + (uint32_t)(r * PQB) + cbyte,
                       (const char*)(g_kh + (size_t)(col0 + r) * D_MODEL + h * HDIM) + cbyte);
        }
        for (int i = tid; i < 64 * 16; i += 256) {
            int r = i >> 4, cbyte = (i & 15) << 4;
            cp_async16(vbase + (uint32_t)(r * PVB) + cbyte,
                       (const char*)(g_vt + (size_t)(h * HDIM + r) * S_LEN + col0) + cbyte);
        }
        cp_commit();
    };
    loadKV(0);

    float oacc[8][4];
#pragma unroll
    for (int j = 0; j < 8; j++)
#pragma unroll
        for (int q = 0; q < 4; q++) oacc[j][q] = 0.f;

    for (int tb = 0; tb < ntb; tb++) {
        if (tb + 1 < ntb) { loadKV(tb + 1); cp_wait<1>(); }
        else              { cp_wait<0>(); }
        bar_sync(barid, 256);

        uint32_t kbase = sb + OFF_K + (uint32_t)(tb & 1) * QSZ;
        uint32_t vbase = sb + OFF_V + (uint32_t)(tb & 1) * VSZ;

        const bool diag = (tb == sblk);
        const int pmax  = diag ? (wid + 1) : 8;
        const int nfmax = diag ? (2 * wid + 2) : 16;

        // ---- MMA1: S[16 x 128] per warp, 1-pass ----
        float sacc[16][4];
#pragma unroll
        for (int j = 0; j < 16; j++)
#pragma unroll
            for (int q = 0; q < 4; q++) sacc[j][q] = 0.f;

        const uint32_t koff = kbase + koff_l;
#pragma unroll
        for (int ks = 0; ks < 4; ks++) {
            const uint32_t ko = (uint32_t)(ks * 32);
            uint32_t ah[4];
            LDSM_X4(ah, qoff + ko);
#pragma unroll
            for (int p = 0; p < 8; p++) {
                if (p < pmax) {
                    uint32_t bh[4];
                    LDSM_X4(bh, koff + (uint32_t)(p * 16 * PQB) + ko);
                    mma16816(sacc[2*p],   ah, bh);
                    mma16816(sacc[2*p+1], ah, bh + 2);
                }
            }
        }

        // ---- mask + exp partial column sums (MUFU) ----
        const int r0 = row0 + wid * 16 + (lane >> 2);
        const int r1 = r0 + 8;
        const int cb2 = (tb << 7) + 2 * (lane & 3);
#pragma unroll
        for (int nf = 0; nf < 16; nf++) {
            float eA = 0.f, eB = 0.f;
            if (nf < nfmax) {
                const int c0 = cb2 + nf * 8;
                float s0 = sacc[nf][0], s1 = sacc[nf][1];
                float s2 = sacc[nf][2], s3 = sacc[nf][3];
                bool m0 = true, m1 = true, m2 = true, m3 = true;
                if (diag) {
                    m0 = (c0 <= r0); m1 = (c0 + 1 <= r0);
                    m2 = (c0 <= r1); m3 = (c0 + 1 <= r1);
                    s0 = m0 ? s0 : 0.f; s1 = m1 ? s1 : 0.f;
                    s2 = m2 ? s2 : 0.f; s3 = m3 ? s3 : 0.f;
                    sacc[nf][0] = s0; sacc[nf][1] = s1;
                    sacc[nf][2] = s2; sacc[nf][3] = s3;
                }
                float e0 = __expf(s0), e1 = __expf(s1);
                float e2 = __expf(s2), e3 = __expf(s3);
                if (diag) {
                    e0 = m0 ? e0 : 0.f; e1 = m1 ? e1 : 0.f;
                    e2 = m2 ? e2 : 0.f; e3 = m3 ? e3 : 0.f;
                }
                eA = e0 + e2; eB = e1 + e3;
                eA += __shfl_xor_sync(0xffffffffu, eA, 4);
                eA += __shfl_xor_sync(0xffffffffu, eA, 8);
                eA += __shfl_xor_sync(0xffffffffu, eA, 16);
                eB += __shfl_xor_sync(0xffffffffu, eB, 4);
                eB += __shfl_xor_sync(0xffffffffu, eB, 8);
                eB += __shfl_xor_sync(0xffffffffu, eB, 16);
            }
            if (lane < 4) {
                spart[wid * 128 + nf * 8 + 2 * lane]     = eA;
                spart[wid * 128 + nf * 8 + 2 * lane + 1] = eB;
            }
        }

        // ---- MMA2: O += S_hi @ V_hi^T, 1-pass ----
        const uint32_t voff = vbase + voff_l;
#pragma unroll
        for (int kc = 0; kc < 8; kc++) {
            if (kc < pmax) {
                uint32_t ahi[4];
                ahi[0] = pack2h(sacc[2*kc][0],   sacc[2*kc][1]);
                ahi[1] = pack2h(sacc[2*kc][2],   sacc[2*kc][3]);
                ahi[2] = pack2h(sacc[2*kc+1][0], sacc[2*kc+1][1]);
                ahi[3] = pack2h(sacc[2*kc+1][2], sacc[2*kc+1][3]);
                const uint32_t ko = (uint32_t)(kc * 32);
#pragma unroll
                for (int p = 0; p < 4; p++) {
                    uint32_t bh[4];
                    LDSM_X4(bh, voff + (uint32_t)(p * 16 * PVB) + ko);
                    mma16816(oacc[2*p],   ahi, bh);
                    mma16816(oacc[2*p+1], ahi, bh + 2);
                }
            }
        }

        bar_sync(barid, 256);
        if (tid < 128) {
            float s = 0.f;
#pragma unroll
            for (int w = 0; w < 8; w++) s += spart[w * 128 + tid];
            g_part[((h * 16 + sblk) << 11) + (tb << 7) + tid] = s;
        }
    }

    // ---- epilogue: Z_hi = fp16(O) ----
    {
        const int r0 = row0 + wid * 16 + (lane >> 2);
        const int cb2 = 2 * (lane & 3);
#pragma unroll
        for (int nf = 0; nf < 8; nf++) {
            const int col = h * HDIM + nf * 8 + cb2;
            *(uint32_t*)(g_zh + (size_t)r0 * D_MODEL + col)       = pack2h(oacc[nf][0], oacc[nf][1]);
            *(uint32_t*)(g_zh + (size_t)(r0 + 8) * D_MODEL + col) = pack2h(oacc[nf][2], oacc[nf][3]);
        }
    }
}

// ---------------------------------------------------------------------------
// Parallel L + partial c: grid(16 segs, 16 heads), 256 threads.
// ---------------------------------------------------------------------------
__global__ __launch_bounds__(256) void lse_c_part()
{
    __shared__ float Ls[128];
    __shared__ float part[4][HDIM];
    const int seg = blockIdx.x, h = blockIdx.y;
    const int tid = threadIdx.x;

    if (tid < 128) {
        const int t = (seg << 7) + tid;
        float acc = (float)t;
        for (int sbk = seg; sbk < 16; sbk++)
            acc += g_part[((h * 16 + sbk) << 11) + t];
        Ls[tid] = logf(acc);
    }
    __syncthreads();

    const int v = tid & 63;
    const int g = tid >> 6;
    const __half2* th = (const __half2*)(g_vt + (size_t)(h * HDIM + v) * S_LEN
                                         + (seg << 7) + (g << 5));
    const float* lp = Ls + (g << 5);
    float s0 = 0.f, s1 = 0.f;
#pragma unroll
    for (int i = 0; i < 16; i++) {
        float2 hv = __half22float2(th[i]);
        s0 = fmaf(lp[2 * i],     hv.x, s0);
        s1 = fmaf(lp[2 * i + 1], hv.y, s1);
    }
    part[g][v] = s0 + s1;
    __syncthreads();
    if (g == 0)
        g_cpart[(h * 16 + seg) * HDIM + v] =
            (part[0][v] + part[1][v]) + (part[2][v] + part[3][v]);
}

// ---------------------------------------------------------------------------
// Merged fold + bias adjust: each CTA folds g_cpart into smem cs[1024]
// (same seg order -> bit-identical c), then 8 warps each compute one row dot.
// grid(128) x 256.
// ---------------------------------------------------------------------------
__global__ __launch_bounds__(256) void bias_adjust(
    const float* __restrict__ WOw, const float* __restrict__ WOb)
{
    __shared__ float cs[D_MODEL];
    const int tid = threadIdx.x, lane = tid & 31, wid = tid >> 5;

    for (int j = tid; j < D_MODEL; j += 256) {
        const int h = j >> 6, v = j & 63;
        float s = 0.f;
#pragma unroll
        for (int seg = 0; seg < 16; seg++)
            s += g_cpart[(h * 16 + seg) * HDIM + v];
        cs[j] = s;
    }
    __syncthreads();

    const int row = blockIdx.x * 8 + wid;
    const float* wr = WOw + (size_t)row * D_MODEL;
    float s = 0.f;
    for (int j = lane; j < D_MODEL; j += 32)
        s = fmaf(wr[j], cs[j], s);
#pragma unroll
    for (int o = 16; o > 0; o >>= 1) s += __shfl_xor_sync(0xffffffffu, s, o);
    if (lane == 0) g_badj[row] = WOb[row] - s;
}

// ---------------------------------------------------------------------------
// One-shot fp32 -> fp16 conversion: 3 inputs + 4 weights, hi only.
// ---------------------------------------------------------------------------
__global__ __launch_bounds__(256) void split_all(
    const float4* __restrict__ Qin, const float4* __restrict__ Kin, const float4* __restrict__ Vin,
    const float4* __restrict__ WQw, const float4* __restrict__ WKw,
    const float4* __restrict__ WVw, const float4* __restrict__ WOw)
{
    const int b = blockIdx.x;
    const float4* src;
    uint4* hi;
    int rb;
    if (b < 3072) {
        const int t = b >> 10; rb = b & 1023;
        src = (t == 0) ? Qin : (t == 1) ? Kin : Vin;
        hi = (uint4*)((t == 0) ? g_iq : (t == 1) ? g_ik : g_iv);
    } else {
        const int bb = b - 3072, t = bb >> 9; rb = bb & 511;
        src = (t == 0) ? WQw : (t == 1) ? WKw : (t == 2) ? WVw : WOw;
        hi = (uint4*)((t == 0) ? g_wq : (t == 1) ? g_wk : (t == 2) ? g_wv : g_wo);
    }
    const int i = rb * 256 + threadIdx.x;
    float4 a = src[2 * i], c = src[2 * i + 1];
    hi[i] = make_uint4(pack2h(a.x, a.y), pack2h(a.z, a.w),
                       pack2h(c.x, c.y), pack2h(c.z, c.w));
}

// ---------------------------------------------------------------------------
extern "C" void kernel_launch(void* const* d_in, const int* in_sizes, int n_in,
                              void* d_out, int out_size)
{
    const float* Qin = (const float*)d_in[0];
    const float* Kin = (const float*)d_in[1];
    const float* Vin = (const float*)d_in[2];
    const float* WQw = (const float*)d_in[3];
    const float* WQb = (const float*)d_in[4];
    const float* WKw = (const float*)d_in[5];
    const float* WKb = (const float*)d_in[6];
    const float* WVw = (const float*)d_in[7];
    const float* WVb = (const float*)d_in[8];
    const float* WOw = (const float*)d_in[9];
    const float* WOb = (const float*)d_in[10];
    float* Out = (float*)d_out;

    cudaFuncSetAttribute(gemm_qkv,   cudaFuncAttributeMaxDynamicSharedMemorySize, SMEM_PROJ);
    cudaFuncSetAttribute(gemm_out,   cudaFuncAttributeMaxDynamicSharedMemorySize, SMEM_PROJ);
    cudaFuncSetAttribute(fused_attn, cudaFuncAttributeMaxDynamicSharedMemorySize, FATTN_SMEM);

    dim3 blk(256);

    // 1) fp16 conversions
    split_all<<<5120, blk>>>((const float4*)Qin, (const float4*)Kin, (const float4*)Vin,
                             (const float4*)WQw, (const float4*)WKw,
                             (const float4*)WVw, (const float4*)WOw);

    // 2) Q/K/V projections (V^T staged in smem, coalesced write)
    dim3 gqkv(D_MODEL / 128, S_LEN / 128, 3);
    gemm_qkv<<<gqkv, blk, SMEM_PROJ>>>(WQb, WKb, WVb);

    // 3) fused attention (512 threads, 2 concurrent warp-groups)
    dim3 gfa(8, NHEAD);
    fused_attn<<<gfa, dim3(512), FATTN_SMEM>>>();

    // 4) parallel L + partial c, then merged fold+bias
    dim3 glc(16, NHEAD);
    lse_c_part<<<glc, blk>>>();
    bias_adjust<<<128, blk>>>(WOw, WOb);

    // 5) output projection with folded bias
    dim3 gout(D_MODEL / 128, S_LEN / 128);
    gemm_out<<<gout, blk, SMEM_PROJ>>>(Out);
}